// round 1
// baseline (speedup 1.0000x reference)
#include <cuda_runtime.h>
#include <stdint.h>

#define NB 4          // batch
#define MB 50         // gt boxes per batch
#define KB 240000     // anchors
#define NK (NB*KB)
#define SELK 256      // NUM_FG == NUM_BG == 256

// ---------------- scratch (no allocations allowed) ----------------
__device__ uint8_t      g_flags[NK];        // 0 = neither, 1 = pos, 2 = neg
__device__ unsigned int g_hist[8][256];     // radix histograms per selection
__device__ unsigned int g_prefix[8];
__device__ int          g_kk[8];
__device__ int          g_done[8];
__device__ unsigned int g_thresh[8];        // key of the 256th-largest member

__device__ __forceinline__ unsigned int fkey(float f) {
    unsigned int u = __float_as_uint(f);
    return (u & 0x80000000u) ? ~u : (u | 0x80000000u);  // order-preserving
}

// ---------------- init selection state ----------------
__global__ void at_init_kernel() {
    int t = threadIdx.x;
    if (t < 8) { g_prefix[t] = 0u; g_kk[t] = SELK; g_done[t] = 0; g_thresh[t] = 0u; }
    for (int i = t; i < 8 * 256; i += blockDim.x)
        ((unsigned int*)g_hist)[i] = 0u;
}

// ---------------- main: IoU max/argmax, targets, flags ----------------
__global__ void at_main_kernel(const float4* __restrict__ anchors,
                               const float4* __restrict__ gt_boxes,
                               const int*    __restrict__ gt_labels,
                               float*        __restrict__ out) {
    __shared__ float4 s_gt[NB * MB];
    __shared__ float  s_area[NB * MB];
    __shared__ float  s_lab[NB * MB];
    for (int i = threadIdx.x; i < NB * MB; i += blockDim.x) {
        float4 g = gt_boxes[i];
        s_gt[i]   = g;
        s_area[i] = __fmul_rn(__fsub_rn(g.z, g.x), __fsub_rn(g.w, g.y));
        s_lab[i]  = (float)gt_labels[i];
    }
    __syncthreads();

    int k = blockIdx.x * blockDim.x + threadIdx.x;
    if (k >= KB) return;

    float4 a = anchors[k];
    float area_a = __fmul_rn(__fsub_rn(a.z, a.x), __fsub_rn(a.w, a.y));
    float aw  = a.z - a.x,        ah  = a.w - a.y;
    float acx = a.x + 0.5f * aw,  acy = a.y + 0.5f * ah;

    #pragma unroll 1
    for (int n = 0; n < NB; ++n) {
        const float4* gt_n = &s_gt[n * MB];
        const float*  ar_n = &s_area[n * MB];

        float best_i, best_d; int best_m = 0;
        {
            float4 g = gt_n[0];
            float w = fmaxf(__fsub_rn(fminf(a.z, g.z), fmaxf(a.x, g.x)), 0.f);
            float h = fmaxf(__fsub_rn(fminf(a.w, g.w), fmaxf(a.y, g.y)), 0.f);
            best_i = __fmul_rn(w, h);
            best_d = __fadd_rn(__fsub_rn(__fadd_rn(area_a, ar_n[0]), best_i), 1e-8f);
        }
        #pragma unroll 7
        for (int m = 1; m < MB; ++m) {
            float4 g = gt_n[m];
            float w = fmaxf(__fsub_rn(fminf(a.z, g.z), fmaxf(a.x, g.x)), 0.f);
            float h = fmaxf(__fsub_rn(fminf(a.w, g.w), fmaxf(a.y, g.y)), 0.f);
            float inter = __fmul_rn(w, h);
            float denom = __fadd_rn(__fsub_rn(__fadd_rn(area_a, ar_n[m]), inter), 1e-8f);
            // division-free max/argmax: inter/denom > best_i/best_d  <=>  inter*best_d > best_i*denom
            float lhs  = __fmul_rn(inter, best_d);
            float rhs  = __fmul_rn(best_i, denom);
            float diff = lhs - rhs;
            float mx   = fmaxf(lhs, rhs);
            bool better;
            if (fabsf(diff) <= 5e-6f * mx && mx > 0.f) {
                // borderline: replicate reference fp32-division comparison exactly
                better = __fdiv_rn(inter, denom) > __fdiv_rn(best_i, best_d);
            } else {
                better = diff > 0.f;
            }
            if (better) { best_i = inter; best_d = denom; best_m = m; }
        }

        bool pos, neg;
        {
            float t7 = __fmul_rn(0.7f, best_d);
            float d7 = __fsub_rn(best_i, t7);
            if (fabsf(d7) <= 5e-6f * t7) pos = (__fdiv_rn(best_i, best_d) >= 0.7f);
            else                          pos = (d7 >= 0.f);
            float t3 = __fmul_rn(0.3f, best_d);
            float d3 = __fsub_rn(best_i, t3);
            if (fabsf(d3) <= 5e-6f * t3) neg = (__fdiv_rn(best_i, best_d) < 0.3f);
            else                          neg = (d3 < 0.f);
        }

        int idx = n * KB + k;
        g_flags[idx] = pos ? (uint8_t)1 : (neg ? (uint8_t)2 : (uint8_t)0);
        out[idx] = pos ? s_lab[n * MB + best_m] : 0.f;

        float4 r = make_float4(0.f, 0.f, 0.f, 0.f);
        if (pos) {  // rare: whole warps skip the logf path
            float4 g  = gt_n[best_m];
            float gw  = g.z - g.x,       gh  = g.w - g.y;
            float gcx = g.x + 0.5f * gw, gcy = g.y + 0.5f * gh;
            r.x = (gcx - acx) / aw;
            r.y = (gcy - acy) / ah;
            r.z = logf(gw / aw);
            r.w = logf(gh / ah);
        }
        ((float4*)(out + NK))[idx] = r;
    }
}

// ---------------- radix-select pass: histogram ----------------
__global__ void at_hist_kernel(const float* __restrict__ scores, int pass) {
    int sel = blockIdx.y;                 // sel = n*2 + (0:pos, 1:neg)
    if (g_done[sel]) return;
    int n = sel >> 1;
    uint8_t want = (uint8_t)((sel & 1) + 1);

    __shared__ unsigned int h[256];
    for (int i = threadIdx.x; i < 256; i += blockDim.x) h[i] = 0u;
    __syncthreads();

    unsigned int prefix = g_prefix[sel];
    int shift = 24 - 8 * pass;
    int per   = (KB + gridDim.x - 1) / gridDim.x;
    int start = blockIdx.x * per;
    int end   = min(start + per, KB);

    const float*   srow = scores  + n * KB;
    const uint8_t* frow = g_flags + n * KB;

    for (int k = start + threadIdx.x; k < end; k += blockDim.x) {
        if (frow[k] != want) continue;
        unsigned int key = fkey(srow[k]);
        if (pass && ((key >> (shift + 8)) != prefix)) continue;
        atomicAdd(&h[(key >> shift) & 255u], 1u);
    }
    __syncthreads();
    for (int i = threadIdx.x; i < 256; i += blockDim.x)
        if (h[i]) atomicAdd(&g_hist[sel][i], h[i]);
}

// ---------------- radix-select pass: pick bin, update state ----------------
__global__ void at_scan_kernel(int pass) {
    int sel = threadIdx.x;
    if (sel >= 8) return;
    unsigned int* h = g_hist[sel];
    if (!g_done[sel]) {
        int kk = g_kk[sel];
        unsigned int cum = 0; int b = 255;
        for (; b >= 0; --b) { cum += h[b]; if ((int)cum >= kk) break; }
        if (b < 0) {
            // fewer than kk members total (only possible on pass 0): take all members
            g_thresh[sel] = 0u; g_done[sel] = 1;
        } else {
            g_kk[sel] = kk - (int)(cum - h[b]);
            unsigned int pfx = (g_prefix[sel] << 8) | (unsigned int)b;
            g_prefix[sel] = pfx;
            if (pass == 3) g_thresh[sel] = pfx;   // exact key of kth-largest member
        }
    }
    for (int i = 0; i < 256; ++i) h[i] = 0u;      // ready for next pass / next replay
}

// ---------------- finalize: weights = subsample mask ----------------
__global__ void at_final_kernel(const float* __restrict__ scores,
                                float* __restrict__ out) {
    int i = blockIdx.x * blockDim.x + threadIdx.x;
    if (i >= NK) return;
    int n = i / KB;
    uint8_t f = g_flags[i];
    float cw = 0.f, rw = 0.f;
    if (f) {
        unsigned int key = fkey(scores[i]);
        int sel = n * 2 + (int)(f - 1);
        if (key >= g_thresh[sel]) {
            cw = 1.f;
            rw = (f == 1) ? 1.f : 0.f;
        }
    }
    out[5 * NK + i] = cw;
    out[6 * NK + i] = rw;
}

// ---------------- launch ----------------
extern "C" void kernel_launch(void* const* d_in, const int* in_sizes, int n_in,
                              void* d_out, int out_size) {
    const float4* anchors  = (const float4*)d_in[0];   // (K,4) f32
    const float*  scores   = (const float*) d_in[1];   // (N,K) f32
    const float4* gt_boxes = (const float4*)d_in[2];   // (N,M,4) f32
    const int*    gt_lab   = (const int*)   d_in[3];   // (N,M) i32
    float* out = (float*)d_out;  // [cls_t | reg_t | cls_w | reg_w] flattened

    at_init_kernel<<<1, 256>>>();
    at_main_kernel<<<(KB + 255) / 256, 256>>>(anchors, gt_boxes, gt_lab, out);
    for (int p = 0; p < 4; ++p) {
        at_hist_kernel<<<dim3(60, 8), 256>>>(scores, p);
        at_scan_kernel<<<1, 32>>>(p);
    }
    at_final_kernel<<<(NK + 255) / 256, 256>>>(scores, out);
}

// round 2
// speedup vs baseline: 1.1929x; 1.1929x over previous
#include <cuda_runtime.h>
#include <stdint.h>

#define NB 4          // batch
#define MB 50         // gt boxes per batch
#define KB 240000     // anchors
#define NK (NB*KB)
#define SELK 256      // NUM_FG == NUM_BG
#define CAP 65536     // candidate buffer capacity per selection

// ---------------- persistent scratch (no allocations allowed) ----------------
__device__ uint8_t      g_flags[NK];          // 0 none, 1 pos, 2 neg
__device__ unsigned int g_hist[8][65536];     // 16-bit radix histograms (zero-init; re-cleared by at_final)
__device__ unsigned int g_prefix[8];
__device__ int          g_kk[8];
__device__ int          g_done[8];
__device__ unsigned int g_thresh[8];
__device__ unsigned int g_cnt[8];             // cleared by at_final
__device__ unsigned int g_cand[8][CAP];

__device__ __forceinline__ unsigned int fkey(float f) {
    unsigned int u = __float_as_uint(f);
    return (u & 0x80000000u) ? ~u : (u | 0x80000000u);  // order-preserving
}

// ---------------- main: IoU max/argmax, targets, flags, fused histogram ----------------
__global__ void at_main_kernel(const float4* __restrict__ anchors,
                               const float4* __restrict__ gt_boxes,
                               const int*    __restrict__ gt_labels,
                               const float*  __restrict__ scores,
                               float*        __restrict__ out) {
    __shared__ float4 s_gt[MB];
    __shared__ float  s_area[MB];
    __shared__ float  s_lab[MB];
    const int n = blockIdx.y;
    for (int i = threadIdx.x; i < MB; i += blockDim.x) {
        float4 g = gt_boxes[n * MB + i];
        s_gt[i]   = g;
        s_area[i] = __fmul_rn(__fsub_rn(g.z, g.x), __fsub_rn(g.w, g.y));
        s_lab[i]  = (float)gt_labels[n * MB + i];
    }
    __syncthreads();

    int k = blockIdx.x * blockDim.x + threadIdx.x;
    if (k >= KB) return;

    float4 a = anchors[k];
    float area_a = __fmul_rn(__fsub_rn(a.z, a.x), __fsub_rn(a.w, a.y));
    float aw  = a.z - a.x,        ah  = a.w - a.y;
    float acx = a.x + 0.5f * aw,  acy = a.y + 0.5f * ah;

    float best_i, best_d; int best_m = 0;
    {
        float4 g = s_gt[0];
        float w = fmaxf(__fsub_rn(fminf(a.z, g.z), fmaxf(a.x, g.x)), 0.f);
        float h = fmaxf(__fsub_rn(fminf(a.w, g.w), fmaxf(a.y, g.y)), 0.f);
        best_i = __fmul_rn(w, h);
        best_d = __fadd_rn(__fsub_rn(__fadd_rn(area_a, s_area[0]), best_i), 1e-8f);
    }
    #pragma unroll 7
    for (int m = 1; m < MB; ++m) {
        float4 g = s_gt[m];
        float w = fmaxf(__fsub_rn(fminf(a.z, g.z), fmaxf(a.x, g.x)), 0.f);
        float h = fmaxf(__fsub_rn(fminf(a.w, g.w), fmaxf(a.y, g.y)), 0.f);
        float inter = __fmul_rn(w, h);
        float denom = __fadd_rn(__fsub_rn(__fadd_rn(area_a, s_area[m]), inter), 1e-8f);
        // division-free max/argmax: inter/denom > best_i/best_d <=> inter*best_d > best_i*denom
        float lhs  = __fmul_rn(inter, best_d);
        float rhs  = __fmul_rn(best_i, denom);
        float diff = lhs - rhs;
        float mx   = fmaxf(lhs, rhs);
        bool better;
        if (fabsf(diff) <= 5e-6f * mx && mx > 0.f) {
            better = __fdiv_rn(inter, denom) > __fdiv_rn(best_i, best_d);  // rare exact path
        } else {
            better = diff > 0.f;
        }
        if (better) { best_i = inter; best_d = denom; best_m = m; }
    }

    bool pos, neg;
    {
        float t7 = __fmul_rn(0.7f, best_d);
        float d7 = __fsub_rn(best_i, t7);
        if (fabsf(d7) <= 5e-6f * t7) pos = (__fdiv_rn(best_i, best_d) >= 0.7f);
        else                          pos = (d7 >= 0.f);
        float t3 = __fmul_rn(0.3f, best_d);
        float d3 = __fsub_rn(best_i, t3);
        if (fabsf(d3) <= 5e-6f * t3) neg = (__fdiv_rn(best_i, best_d) < 0.3f);
        else                          neg = (d3 < 0.f);
    }

    int idx = n * KB + k;
    uint8_t f = pos ? (uint8_t)1 : (neg ? (uint8_t)2 : (uint8_t)0);
    g_flags[idx] = f;
    out[idx] = pos ? s_lab[best_m] : 0.f;

    float4 r = make_float4(0.f, 0.f, 0.f, 0.f);
    if (pos) {  // rare: whole warps usually skip
        float4 g  = s_gt[best_m];
        float gw  = g.z - g.x,       gh  = g.w - g.y;
        float gcx = g.x + 0.5f * gw, gcy = g.y + 0.5f * gh;
        r.x = (gcx - acx) / aw;
        r.y = (gcy - acy) / ah;
        r.z = logf(gw / aw);
        r.w = logf(gh / ah);
    }
    ((float4*)(out + NK))[idx] = r;

    // fused 16-bit radix histogram (top 16 key bits)
    if (f) {
        unsigned int key = fkey(scores[idx]);
        atomicAdd(&g_hist[n * 2 + (int)(f - 1)][key >> 16], 1u);
    }
}

// ---------------- parallel suffix scan over 65536 bins per selection ----------------
__global__ void at_scanA_kernel() {
    const int sel = blockIdx.x;
    const int t   = threadIdx.x;           // 1024 threads, 64 bins each
    const unsigned int* __restrict__ h = g_hist[sel];
    __shared__ unsigned int s[1024];

    const int base = t * 64;
    unsigned int sum = 0;
    #pragma unroll 8
    for (int i = 0; i < 64; ++i) sum += h[base + i];
    s[t] = sum;
    __syncthreads();
    // inclusive suffix scan: s[t] = sum over chunks u >= t
    for (int off = 1; off < 1024; off <<= 1) {
        unsigned int v = (t + off < 1024) ? s[t + off] : 0u;
        __syncthreads();
        s[t] += v;
        __syncthreads();
    }
    const unsigned int total = s[0];
    const unsigned int above = s[t] - sum;     // count in bins strictly above this chunk
    const unsigned int kk = SELK;

    if (t == 0) {
        g_done[sel] = (total < kk);
        if (total < kk) g_thresh[sel] = 0u;    // take all members
    }
    if (total >= kk && above < kk && above + sum >= kk) {   // exactly one thread
        unsigned int cum = above;
        for (int b = 63; b >= 0; --b) {
            unsigned int c = h[base + b];
            if (cum + c >= kk) {
                g_prefix[sel] = (unsigned int)(base + b);
                g_kk[sel]     = (int)(kk - cum);
                break;
            }
            cum += c;
        }
    }
}

// ---------------- collect candidates sharing the chosen 16-bit prefix ----------------
__global__ void at_collect_kernel(const float* __restrict__ scores) {
    const int sel = blockIdx.y;
    if (g_done[sel]) return;
    const int n = sel >> 1;
    const uint8_t want = (uint8_t)((sel & 1) + 1);
    const unsigned int pfx = g_prefix[sel];

    int k = blockIdx.x * blockDim.x + threadIdx.x;
    if (k >= KB) return;
    int idx = n * KB + k;
    if (g_flags[idx] != want) return;
    unsigned int key = fkey(scores[idx]);
    if ((key >> 16) != pfx) return;
    unsigned int slot = atomicAdd(&g_cnt[sel], 1u);
    if (slot < CAP) g_cand[sel][slot] = key;
}

// ---------------- exact low-16-bit selection among candidates ----------------
__global__ void at_scanB_kernel() {
    const int sel = blockIdx.x;
    if (g_done[sel]) return;
    const int t = threadIdx.x;              // 256 threads
    __shared__ unsigned int hist[256];
    __shared__ unsigned int s_b1, s_k2;

    const int c = (int)min(g_cnt[sel], (unsigned int)CAP);
    const unsigned int kk = (unsigned int)g_kk[sel];

    hist[t] = 0; __syncthreads();
    for (int i = t; i < c; i += 256)
        atomicAdd(&hist[(g_cand[sel][i] >> 8) & 255u], 1u);
    __syncthreads();
    if (t == 0) {
        unsigned int cum = 0;
        for (int b = 255; b >= 0; --b) {
            unsigned int h = hist[b];
            if (cum + h >= kk) { s_b1 = (unsigned int)b; s_k2 = kk - cum; break; }
            cum += h;
        }
    }
    __syncthreads();
    const unsigned int b1 = s_b1, k2 = s_k2;
    hist[t] = 0; __syncthreads();
    for (int i = t; i < c; i += 256) {
        unsigned int key = g_cand[sel][i];
        if (((key >> 8) & 255u) == b1) atomicAdd(&hist[key & 255u], 1u);
    }
    __syncthreads();
    if (t == 0) {
        unsigned int cum = 0;
        for (int b = 255; b >= 0; --b) {
            unsigned int h = hist[b];
            if (cum + h >= k2) {
                g_thresh[sel] = (g_prefix[sel] << 16) | (b1 << 8) | (unsigned int)b;
                break;
            }
            cum += h;
        }
    }
}

// ---------------- finalize weights + clear state for next replay ----------------
__global__ void at_final_kernel(const float* __restrict__ scores,
                                float* __restrict__ out) {
    // clear hist/cnt for the next graph replay (first call relies on zero-init)
    unsigned int gid = (blockIdx.y * gridDim.x + blockIdx.x) * blockDim.x + threadIdx.x;
    if (gid < 8u * 65536u) ((unsigned int*)g_hist)[gid] = 0u;
    if (gid < 8u) g_cnt[gid] = 0u;

    const int n = blockIdx.y;
    int k = blockIdx.x * blockDim.x + threadIdx.x;
    if (k >= KB) return;
    int idx = n * KB + k;
    uint8_t f = g_flags[idx];
    float cw = 0.f, rw = 0.f;
    if (f) {
        unsigned int key = fkey(scores[idx]);
        int sel = n * 2 + (int)(f - 1);
        if (key >= g_thresh[sel]) {
            cw = 1.f;
            rw = (f == 1) ? 1.f : 0.f;
        }
    }
    out[5 * NK + idx] = cw;
    out[6 * NK + idx] = rw;
}

// ---------------- launch ----------------
extern "C" void kernel_launch(void* const* d_in, const int* in_sizes, int n_in,
                              void* d_out, int out_size) {
    const float4* anchors  = (const float4*)d_in[0];   // (K,4) f32
    const float*  scores   = (const float*) d_in[1];   // (N,K) f32
    const float4* gt_boxes = (const float4*)d_in[2];   // (N,M,4) f32
    const int*    gt_lab   = (const int*)   d_in[3];   // (N,M) i32
    float* out = (float*)d_out;  // [cls_t | reg_t | cls_w | reg_w]

    const int GB = (KB + 255) / 256;   // 938
    at_main_kernel   <<<dim3(GB, NB), 256>>>(anchors, gt_boxes, gt_lab, scores, out);
    at_scanA_kernel  <<<8, 1024>>>();
    at_collect_kernel<<<dim3(GB, 8), 256>>>(scores);
    at_scanB_kernel  <<<8, 256>>>();
    at_final_kernel  <<<dim3(GB, NB), 256>>>(scores, out);
}